// round 5
// baseline (speedup 1.0000x reference)
#include <cuda_runtime.h>

// CHIVE clockwork RNN scan — f32x2 packed version.
// T=2048 serial steps, B=2048 batch, H=32.
// One warp handles TWO batch elements (packed into f32x2 lanes); lane = hidden j.
// State in shared as (b0,b1) pairs, broadcast LDS.128 (2 hidden x 2 batch per load).
// Syl weights duplicated into per-lane register pairs; f/p weights duplicated in shared.

#define TT 2048
#define BB 2048
#define HH 32
#define DF 8
#define DS 24
#define NW 8                 // warps per block; each warp = 2 batch rows
#define NTHREADS (NW * 32)
#define NBLOCKS (BB / (2 * NW))   // 128

typedef unsigned long long u64;

__device__ __forceinline__ u64 pack2(float lo, float hi) {
    u64 r; asm("mov.b64 %0, {%1,%2};" : "=l"(r) : "f"(lo), "f"(hi)); return r;
}
__device__ __forceinline__ void unpack2(u64 v, float& lo, float& hi) {
    asm("mov.b64 {%0,%1}, %2;" : "=f"(lo), "=f"(hi) : "l"(v));
}
__device__ __forceinline__ u64 dup2(float w) { return pack2(w, w); }
__device__ __forceinline__ u64 fma2(u64 a, u64 b, u64 c) {
    u64 d; asm("fma.rn.f32x2 %0, %1, %2, %3;" : "=l"(d) : "l"(a), "l"(b), "l"(c)); return d;
}
__device__ __forceinline__ u64 add2(u64 a, u64 b) {
    u64 d; asm("add.rn.f32x2 %0, %1, %2;" : "=l"(d) : "l"(a), "l"(b)); return d;
}
__device__ __forceinline__ float fast_tanh(float x) {
    float e = __expf(2.0f * x);
    return 1.0f - __fdividef(2.0f, e + 1.0f);
}
__device__ __forceinline__ u64 tanh2(u64 v) {
    float a, b; unpack2(v, a, b);
    return pack2(fast_tanh(a), fast_tanh(b));
}

__global__ __launch_bounds__(NTHREADS, 1)
void chive_kernel(const float* __restrict__ frnn,
                  const float* __restrict__ phrnn,
                  const float* __restrict__ syl,
                  const float* __restrict__ Wxf, const float* __restrict__ Whf,
                  const float* __restrict__ bfv,
                  const float* __restrict__ Wxp, const float* __restrict__ Whp,
                  const float* __restrict__ bpv,
                  const float* __restrict__ Wxs, const float* __restrict__ Whs,
                  const float* __restrict__ bsv,
                  const int* __restrict__ fclk, const int* __restrict__ pclk,
                  const int* __restrict__ sfreq,
                  float* __restrict__ out)
{
    __shared__ u64 sWhf2[HH * HH];               // duplicated pairs (w,w), [k][j]
    __shared__ u64 sWhp2[HH * HH];
    __shared__ u64 sWxf2[DF * HH];
    __shared__ u64 sWxp2[DF * HH];
    __shared__ unsigned char sflags[TT];
    __shared__ __align__(16) u64 sh[NW][5][HH];  // (b0,b1) pairs: hf, hp, hs0, hs1, hs2
    __shared__ __align__(16) u64 sxs[NW][HH];    // x staging pairs

    const int tid  = threadIdx.x;
    const int w    = tid >> 5;
    const int lane = tid & 31;
    const int b0   = (blockIdx.x * NW + w) * 2;
    const int b1   = b0 + 1;

    // --- block-wide init ---
    for (int i = tid; i < HH * HH; i += NTHREADS) {
        sWhf2[i] = dup2(Whf[i]);
        sWhp2[i] = dup2(Whp[i]);
    }
    for (int i = tid; i < DF * HH; i += NTHREADS) {
        sWxf2[i] = dup2(Wxf[i]);
        sWxp2[i] = dup2(Wxp[i]);
    }
    for (int t = tid; t < TT; t += NTHREADS) {
        int uf = ((t % (fclk[t] + 1)) == 0) ? 1 : 0;
        int up = ((t % (pclk[t] + 1)) == 0) ? 2 : 0;
        int us = (sfreq[t] == 1) ? 4 : 0;
        sflags[t] = (unsigned char)(uf | up | us);
    }
    for (int i = tid; i < NW * 5 * HH; i += NTHREADS)
        ((u64*)sh)[i] = 0ULL;
    __syncthreads();

    // --- per-lane syl weight columns, duplicated into register pairs ---
    u64 whs2[HH], wxs2[HH];
#pragma unroll
    for (int k = 0; k < HH; k++) {
        whs2[k] = dup2(Whs[k * HH + lane]);
        wxs2[k] = dup2(Wxs[k * HH + lane]);
    }
    const u64 bf2 = dup2(bfv[lane]);
    const u64 bp2 = dup2(bpv[lane]);
    const u64 bs2 = dup2(bsv[lane]);

    u64 z0 = 0ULL, z1 = 0ULL;   // cached h_f @ Wx_s, h_p @ Wx_s (pairs)

    const ulonglong2* hf2 = (const ulonglong2*)sh[w][0];
    const ulonglong2* hp2 = (const ulonglong2*)sh[w][1];
    const ulonglong2* s0p = (const ulonglong2*)sh[w][2];
    const ulonglong2* s1p = (const ulonglong2*)sh[w][3];
    const ulonglong2* s2p = (const ulonglong2*)sh[w][4];
    const ulonglong2* xsp = (const ulonglong2*)sxs[w];

    for (int t = 0; t < TT; t++) {
        const int fl = sflags[t];
        if (!fl) continue;                       // warp-uniform: no divergence

        // issue all gmem x loads early to cover latency
        float fx0, fx1, px0, px1, sx0, sx1;
        if ((fl & 1) && lane < DF) {
            const size_t base = ((size_t)t * BB + b0) * DF + lane;
            fx0 = frnn[base];
            fx1 = frnn[base + DF];
        }
        if ((fl & 2) && lane < DF) {
            const size_t base = ((size_t)t * BB + b0) * DF + lane;
            px0 = phrnn[base];
            px1 = phrnn[base + DF];
        }
        if ((fl & 4) && lane < DS) {
            const size_t base = ((size_t)t * BB + b0) * DS + lane;
            sx0 = syl[base];
            sx1 = syl[base + DS];
        }

        // ---------------- f cell ----------------
        if (fl & 1) {
            __syncwarp();
            if (lane < DF) sxs[w][lane] = pack2(fx0, fx1);
            __syncwarp();
            u64 a0 = bf2, a1 = 0ULL;
#pragma unroll
            for (int q = 0; q < 16; q++) {
                ulonglong2 h2 = hf2[q];
                a0 = fma2(h2.x, sWhf2[(2 * q + 0) * HH + lane], a0);
                a1 = fma2(h2.y, sWhf2[(2 * q + 1) * HH + lane], a1);
            }
#pragma unroll
            for (int q = 0; q < 4; q++) {
                ulonglong2 x2 = xsp[q];
                a0 = fma2(x2.x, sWxf2[(2 * q + 0) * HH + lane], a0);
                a1 = fma2(x2.y, sWxf2[(2 * q + 1) * HH + lane], a1);
            }
            u64 hn = tanh2(add2(a0, a1));
            __syncwarp();                        // all lanes done reading old h_f
            sh[w][0][lane] = hn;
            __syncwarp();                        // new h_f visible warp-wide
            // refresh z0 = h_f @ Wx_s (register weights)
            u64 c0 = 0ULL, c1 = 0ULL;
#pragma unroll
            for (int q = 0; q < 16; q++) {
                ulonglong2 h2 = hf2[q];
                c0 = fma2(h2.x, wxs2[2 * q + 0], c0);
                c1 = fma2(h2.y, wxs2[2 * q + 1], c1);
            }
            z0 = add2(c0, c1);
        }

        // ---------------- p cell ----------------
        if (fl & 2) {
            __syncwarp();                        // f's staging readers done
            if (lane < DF) sxs[w][lane] = pack2(px0, px1);
            __syncwarp();
            u64 a0 = bp2, a1 = 0ULL;
#pragma unroll
            for (int q = 0; q < 16; q++) {
                ulonglong2 h2 = hp2[q];
                a0 = fma2(h2.x, sWhp2[(2 * q + 0) * HH + lane], a0);
                a1 = fma2(h2.y, sWhp2[(2 * q + 1) * HH + lane], a1);
            }
#pragma unroll
            for (int q = 0; q < 4; q++) {
                ulonglong2 x2 = xsp[q];
                a0 = fma2(x2.x, sWxp2[(2 * q + 0) * HH + lane], a0);
                a1 = fma2(x2.y, sWxp2[(2 * q + 1) * HH + lane], a1);
            }
            u64 hn = tanh2(add2(a0, a1));
            __syncwarp();
            sh[w][1][lane] = hn;
            __syncwarp();
            u64 c0 = 0ULL, c1 = 0ULL;
#pragma unroll
            for (int q = 0; q < 16; q++) {
                ulonglong2 h2 = hp2[q];
                c0 = fma2(h2.x, wxs2[2 * q + 0], c0);
                c1 = fma2(h2.y, wxs2[2 * q + 1], c1);
            }
            z1 = add2(c0, c1);
        }

        // ---------------- syl cell (3 slabs, register weights) ----------------
        if (fl & 4) {
            __syncwarp();                        // prior staging readers done
            if (lane < DS) sxs[w][lane] = pack2(sx0, sx1);
            __syncwarp();
            u64 p0 = add2(bs2, z0), q0 = 0ULL;
            u64 p1 = add2(bs2, z1), q1 = 0ULL;
            u64 p2 = bs2,           q2 = 0ULL;
#pragma unroll
            for (int q = 0; q < 16; q++) {
                u64 w0 = whs2[2 * q + 0];
                u64 w1 = whs2[2 * q + 1];
                ulonglong2 a2 = s0p[q];
                p0 = fma2(a2.x, w0, p0); q0 = fma2(a2.y, w1, q0);
                ulonglong2 b2 = s1p[q];
                p1 = fma2(b2.x, w0, p1); q1 = fma2(b2.y, w1, q1);
                ulonglong2 c2 = s2p[q];
                p2 = fma2(c2.x, w0, p2); q2 = fma2(c2.y, w1, q2);
            }
#pragma unroll
            for (int q = 0; q < 12; q++) {       // 24 x-pairs (zero-padded tail)
                ulonglong2 x2 = xsp[q];
                p2 = fma2(x2.x, wxs2[2 * q + 0], p2);
                q2 = fma2(x2.y, wxs2[2 * q + 1], q2);
            }
            u64 n0 = tanh2(add2(p0, q0));
            u64 n1 = tanh2(add2(p1, q1));
            u64 n2 = tanh2(add2(p2, q2));
            __syncwarp();
            sh[w][2][lane] = n0;
            sh[w][3][lane] = n1;
            sh[w][4][lane] = n2;
            __syncwarp();
        }
    }

    // output: h_s [3, B, H]
#pragma unroll
    for (int slab = 0; slab < 3; slab++) {
        float lo, hi;
        unpack2(sh[w][2 + slab][lane], lo, hi);
        out[slab * BB * HH + b0 * HH + lane] = lo;
        out[slab * BB * HH + b1 * HH + lane] = hi;
    }
}

extern "C" void kernel_launch(void* const* d_in, const int* in_sizes, int n_in,
                              void* d_out, int out_size) {
    const float* frnn  = (const float*)d_in[0];
    const float* phrnn = (const float*)d_in[1];
    const float* syl   = (const float*)d_in[2];
    const float* Wxf   = (const float*)d_in[3];
    const float* Whf   = (const float*)d_in[4];
    const float* bfv   = (const float*)d_in[5];
    const float* Wxp   = (const float*)d_in[6];
    const float* Whp   = (const float*)d_in[7];
    const float* bpv   = (const float*)d_in[8];
    const float* Wxs   = (const float*)d_in[9];
    const float* Whs   = (const float*)d_in[10];
    const float* bsv   = (const float*)d_in[11];
    const int*   fclk  = (const int*)d_in[12];
    const int*   pclk  = (const int*)d_in[13];
    const int*   sfreq = (const int*)d_in[14];
    float* out = (float*)d_out;

    chive_kernel<<<NBLOCKS, NTHREADS>>>(frnn, phrnn, syl,
                                        Wxf, Whf, bfv,
                                        Wxp, Whp, bpv,
                                        Wxs, Whs, bsv,
                                        fclk, pclk, sfreq, out);
}